// round 12
// baseline (speedup 1.0000x reference)
#include <cuda_runtime.h>
#include <cuda_bf16.h>
#include <cstdint>

// TopDownProjector: for each column [b,c,y,x,:] (D=256 contiguous fp32),
// scan from depth D-1 downward for the first non-zero voxel.
//   out[0 .. N)   = height_field (depth index of hit, 0 if empty)
//   out[N .. 2N)  = seg_map (voxel value at hit, 0 if empty)
//
// TERMINAL. Identical binary measured 8.64/8.93/8.96/8.70 us (rounds 7/9/10/11)
// = pure run-to-run noise. Binding constraint: one mandatory 128B DRAM line
// fill per column (67.5 MB, layout-private lines at 1KB stride) served at the
// HBM3e random-fill efficiency ceiling (~4.2 TB/s cold, DRAM pipe 53%),
// partially offset by harness-determined L2 replay hits. Proven irrelevant:
// datapath (LDG/TMA), MLP 1-8, occupancy 21-83% (more misses don't raise
// random-fill efficiency), cache policy (default/cs/evict_last), grid shape.
// Config: 4 columns/thread, one 32B load per column (top 8 voxels;
// p(unresolved) = (1/9)^8 ~ 2e-8), coalesced float4 stores, 512 x 256.

static constexpr int D = 256;

struct Top8 { float f[8]; };   // depths D-8 .. D-1

__device__ __forceinline__ Top8 ld_top8(const float* p /* colp + D-8 */) {
    uint64_t a, b, c, d;
    asm volatile("ld.global.nc.L2::evict_last.v4.b64 {%0,%1,%2,%3}, [%4];"
                 : "=l"(a), "=l"(b), "=l"(c), "=l"(d)
                 : "l"(p));
    Top8 t;
    t.f[0] = __uint_as_float((uint32_t)a);  t.f[1] = __uint_as_float((uint32_t)(a >> 32));
    t.f[2] = __uint_as_float((uint32_t)b);  t.f[3] = __uint_as_float((uint32_t)(b >> 32));
    t.f[4] = __uint_as_float((uint32_t)c);  t.f[5] = __uint_as_float((uint32_t)(c >> 32));
    t.f[6] = __uint_as_float((uint32_t)d);  t.f[7] = __uint_as_float((uint32_t)(d >> 32));
    return t;
}

__device__ __forceinline__ float2 resolve_col(const float* __restrict__ colp,
                                              const Top8& t) {
    #pragma unroll
    for (int i = 7; i >= 0; --i)
        if (t.f[i] != 0.0f)
            return make_float2((float)(D - 8 + i), t.f[i]);
    // p ~ 2e-8 per column: scalar descent over the remaining depths.
    for (int k = D - 9; k >= 0; --k) {
        float v = __ldg(colp + k);
        if (v != 0.0f) return make_float2((float)k, v);
    }
    return make_float2(0.0f, 0.0f);
}

__global__ void __launch_bounds__(256)
topdown_kernel4(const float* __restrict__ volume,
                float4* __restrict__ height4,
                float4* __restrict__ seg4,
                int n_quads) {
    int q = blockIdx.x * blockDim.x + threadIdx.x;
    if (q >= n_quads) return;

    const float* p0 = volume + ((size_t)q * 4 + 0) * D;
    const float* p1 = volume + ((size_t)q * 4 + 1) * D;
    const float* p2 = volume + ((size_t)q * 4 + 2) * D;
    const float* p3 = volume + ((size_t)q * 4 + 3) * D;

    // Four independent 32B top loads (MLP=4), issued back-to-back.
    Top8 t0 = ld_top8(p0 + (D - 8));
    Top8 t1 = ld_top8(p1 + (D - 8));
    Top8 t2 = ld_top8(p2 + (D - 8));
    Top8 t3 = ld_top8(p3 + (D - 8));

    float2 r0 = resolve_col(p0, t0);
    float2 r1 = resolve_col(p1, t1);
    float2 r2 = resolve_col(p2, t2);
    float2 r3 = resolve_col(p3, t3);

    // Fully coalesced 16B stores per output stream.
    height4[q] = make_float4(r0.x, r1.x, r2.x, r3.x);
    seg4[q]    = make_float4(r0.y, r1.y, r2.y, r3.y);
}

extern "C" void kernel_launch(void* const* d_in, const int* in_sizes, int n_in,
                              void* d_out, int out_size) {
    const float* volume = (const float*)d_in[0];
    float* out = (float*)d_out;

    int n_cols  = in_sizes[0] / D;     // 524288 for [2,1,512,512,256]
    int n_quads = n_cols / 4;

    float4* height4 = (float4*)out;            // height_field, flattened
    float4* seg4    = (float4*)(out + n_cols); // seg_map

    int threads = 256;
    int blocks = (n_quads + threads - 1) / threads;   // 512 blocks
    topdown_kernel4<<<blocks, threads>>>(volume, height4, seg4, n_quads);
}

// round 13
// speedup vs baseline: 1.0036x; 1.0036x over previous
#include <cuda_runtime.h>
#include <cuda_bf16.h>
#include <cstdint>

// TopDownProjector: for each column [b,c,y,x,:] (D=256 contiguous fp32),
// scan from depth D-1 downward for the first non-zero voxel.
//   out[0 .. N)   = height_field (depth index of hit, 0 if empty)
//   out[N .. 2N)  = seg_map (voxel value at hit, 0 if empty)
//
// TERMINAL. Identical binary over 5 runs: 8.64/8.93/8.96/8.70/8.96 us —
// pure run-to-run noise. Binding constraints (all outside kernel control):
//  1. One mandatory private 128B DRAM line fill per column (67.5 MB; 1KB
//     column stride forbids line sharing under any access strategy).
//  2. HBM3e random-line-fill efficiency ceiling (~4.2 TB/s cold; deeper miss
//     queues via higher occupancy made it slower, TMA path identical).
//  3. L2 replay hit fraction is harness-determined (evict_last neutral).
// Proven irrelevant: datapath (LDG/TMA), MLP 1-8, occ 21-83%, cache policy
// (default/cs/evict_last), grid 256-2048 blocks.
// Config: 4 columns/thread, one 32B load per column (top 8 voxels;
// p(unresolved) = (1/9)^8 ~ 2e-8), coalesced float4 stores, 512 x 256.

static constexpr int D = 256;

struct Top8 { float f[8]; };   // depths D-8 .. D-1

__device__ __forceinline__ Top8 ld_top8(const float* p /* colp + D-8 */) {
    uint64_t a, b, c, d;
    asm volatile("ld.global.nc.L2::evict_last.v4.b64 {%0,%1,%2,%3}, [%4];"
                 : "=l"(a), "=l"(b), "=l"(c), "=l"(d)
                 : "l"(p));
    Top8 t;
    t.f[0] = __uint_as_float((uint32_t)a);  t.f[1] = __uint_as_float((uint32_t)(a >> 32));
    t.f[2] = __uint_as_float((uint32_t)b);  t.f[3] = __uint_as_float((uint32_t)(b >> 32));
    t.f[4] = __uint_as_float((uint32_t)c);  t.f[5] = __uint_as_float((uint32_t)(c >> 32));
    t.f[6] = __uint_as_float((uint32_t)d);  t.f[7] = __uint_as_float((uint32_t)(d >> 32));
    return t;
}

__device__ __forceinline__ float2 resolve_col(const float* __restrict__ colp,
                                              const Top8& t) {
    #pragma unroll
    for (int i = 7; i >= 0; --i)
        if (t.f[i] != 0.0f)
            return make_float2((float)(D - 8 + i), t.f[i]);
    // p ~ 2e-8 per column: scalar descent over the remaining depths.
    for (int k = D - 9; k >= 0; --k) {
        float v = __ldg(colp + k);
        if (v != 0.0f) return make_float2((float)k, v);
    }
    return make_float2(0.0f, 0.0f);
}

__global__ void __launch_bounds__(256)
topdown_kernel4(const float* __restrict__ volume,
                float4* __restrict__ height4,
                float4* __restrict__ seg4,
                int n_quads) {
    int q = blockIdx.x * blockDim.x + threadIdx.x;
    if (q >= n_quads) return;

    const float* p0 = volume + ((size_t)q * 4 + 0) * D;
    const float* p1 = volume + ((size_t)q * 4 + 1) * D;
    const float* p2 = volume + ((size_t)q * 4 + 2) * D;
    const float* p3 = volume + ((size_t)q * 4 + 3) * D;

    // Four independent 32B top loads (MLP=4), issued back-to-back.
    Top8 t0 = ld_top8(p0 + (D - 8));
    Top8 t1 = ld_top8(p1 + (D - 8));
    Top8 t2 = ld_top8(p2 + (D - 8));
    Top8 t3 = ld_top8(p3 + (D - 8));

    float2 r0 = resolve_col(p0, t0);
    float2 r1 = resolve_col(p1, t1);
    float2 r2 = resolve_col(p2, t2);
    float2 r3 = resolve_col(p3, t3);

    // Fully coalesced 16B stores per output stream.
    height4[q] = make_float4(r0.x, r1.x, r2.x, r3.x);
    seg4[q]    = make_float4(r0.y, r1.y, r2.y, r3.y);
}

extern "C" void kernel_launch(void* const* d_in, const int* in_sizes, int n_in,
                              void* d_out, int out_size) {
    const float* volume = (const float*)d_in[0];
    float* out = (float*)d_out;

    int n_cols  = in_sizes[0] / D;     // 524288 for [2,1,512,512,256]
    int n_quads = n_cols / 4;

    float4* height4 = (float4*)out;            // height_field, flattened
    float4* seg4    = (float4*)(out + n_cols); // seg_map

    int threads = 256;
    int blocks = (n_quads + threads - 1) / threads;   // 512 blocks
    topdown_kernel4<<<blocks, threads>>>(volume, height4, seg4, n_quads);
}

// round 14
// speedup vs baseline: 1.0332x; 1.0295x over previous
#include <cuda_runtime.h>
#include <cuda_bf16.h>
#include <cstdint>

// TopDownProjector: for each column [b,c,y,x,:] (D=256 contiguous fp32),
// scan from depth D-1 downward for the first non-zero voxel.
//   out[0 .. N)   = height_field (depth index of hit, 0 if empty)
//   out[N .. 2N)  = seg_map (voxel value at hit, 0 if empty)
//
// TERMINAL. Identical binary over 6 runs: 8.64/8.93/8.96/8.70/8.96/8.93 us —
// run-to-run noise only. Binding constraints (all outside kernel control):
//  1. One mandatory 128B line-granular DRAM fill per column (67.5 MB; 1KB
//     column stride forbids line sharing; fill granularity not controllable
//     from the kernel — 16B/32B/TMA requests all measured identical).
//  2. HBM3e random-line-fill efficiency ceiling (~4.2 TB/s cold; higher
//     occupancy/deeper miss queues were slower, TMA path identical).
//  3. L2 replay hit fraction is harness-determined (evict_last neutral).
// Config: 4 columns/thread, one 32B load per column (top 8 voxels;
// p(unresolved) = (1/9)^8 ~ 2e-8), coalesced float4 stores, 512 x 256.

static constexpr int D = 256;

struct Top8 { float f[8]; };   // depths D-8 .. D-1

__device__ __forceinline__ Top8 ld_top8(const float* p /* colp + D-8 */) {
    uint64_t a, b, c, d;
    asm volatile("ld.global.nc.L2::evict_last.v4.b64 {%0,%1,%2,%3}, [%4];"
                 : "=l"(a), "=l"(b), "=l"(c), "=l"(d)
                 : "l"(p));
    Top8 t;
    t.f[0] = __uint_as_float((uint32_t)a);  t.f[1] = __uint_as_float((uint32_t)(a >> 32));
    t.f[2] = __uint_as_float((uint32_t)b);  t.f[3] = __uint_as_float((uint32_t)(b >> 32));
    t.f[4] = __uint_as_float((uint32_t)c);  t.f[5] = __uint_as_float((uint32_t)(c >> 32));
    t.f[6] = __uint_as_float((uint32_t)d);  t.f[7] = __uint_as_float((uint32_t)(d >> 32));
    return t;
}

__device__ __forceinline__ float2 resolve_col(const float* __restrict__ colp,
                                              const Top8& t) {
    #pragma unroll
    for (int i = 7; i >= 0; --i)
        if (t.f[i] != 0.0f)
            return make_float2((float)(D - 8 + i), t.f[i]);
    // p ~ 2e-8 per column: scalar descent over the remaining depths.
    for (int k = D - 9; k >= 0; --k) {
        float v = __ldg(colp + k);
        if (v != 0.0f) return make_float2((float)k, v);
    }
    return make_float2(0.0f, 0.0f);
}

__global__ void __launch_bounds__(256)
topdown_kernel4(const float* __restrict__ volume,
                float4* __restrict__ height4,
                float4* __restrict__ seg4,
                int n_quads) {
    int q = blockIdx.x * blockDim.x + threadIdx.x;
    if (q >= n_quads) return;

    const float* p0 = volume + ((size_t)q * 4 + 0) * D;
    const float* p1 = volume + ((size_t)q * 4 + 1) * D;
    const float* p2 = volume + ((size_t)q * 4 + 2) * D;
    const float* p3 = volume + ((size_t)q * 4 + 3) * D;

    // Four independent 32B top loads (MLP=4), issued back-to-back.
    Top8 t0 = ld_top8(p0 + (D - 8));
    Top8 t1 = ld_top8(p1 + (D - 8));
    Top8 t2 = ld_top8(p2 + (D - 8));
    Top8 t3 = ld_top8(p3 + (D - 8));

    float2 r0 = resolve_col(p0, t0);
    float2 r1 = resolve_col(p1, t1);
    float2 r2 = resolve_col(p2, t2);
    float2 r3 = resolve_col(p3, t3);

    // Fully coalesced 16B stores per output stream.
    height4[q] = make_float4(r0.x, r1.x, r2.x, r3.x);
    seg4[q]    = make_float4(r0.y, r1.y, r2.y, r3.y);
}

extern "C" void kernel_launch(void* const* d_in, const int* in_sizes, int n_in,
                              void* d_out, int out_size) {
    const float* volume = (const float*)d_in[0];
    float* out = (float*)d_out;

    int n_cols  = in_sizes[0] / D;     // 524288 for [2,1,512,512,256]
    int n_quads = n_cols / 4;

    float4* height4 = (float4*)out;            // height_field, flattened
    float4* seg4    = (float4*)(out + n_cols); // seg_map

    int threads = 256;
    int blocks = (n_quads + threads - 1) / threads;   // 512 blocks
    topdown_kernel4<<<blocks, threads>>>(volume, height4, seg4, n_quads);
}